// round 8
// baseline (speedup 1.0000x reference)
#include <cuda_runtime.h>
#include <math.h>

namespace {
constexpr int kB = 256;   // batch
constexpr int kT = 256;   // timesteps
constexpr int kI = 512;   // input dim
constexpr int kH = 1024;  // hidden dim
}

// ---------------- packed f32x2 helpers (SASS FFMA2 path) --------------------
__device__ __forceinline__ unsigned long long pack2(float x, float y) {
  unsigned long long r;
  asm("mov.b64 %0, {%1, %2};" : "=l"(r) : "f"(x), "f"(y));
  return r;
}
__device__ __forceinline__ void fma2(unsigned long long& d, unsigned long long a,
                                     unsigned long long b) {
  asm("fma.rn.f32x2 %0, %1, %2, %0;" : "+l"(d) : "l"(a), "l"(b));
}
__device__ __forceinline__ float2 unpack2(unsigned long long v) {
  float2 r;
  asm("mov.b64 {%0, %1}, %2;" : "=f"(r.x), "=f"(r.y) : "l"(v));
  return r;
}
__device__ __forceinline__ void pf_l2(const float* p) {
  asm volatile("prefetch.global.L2 [%0];" ::"l"(p));
}

// ---------------- device scratch (no allocations allowed) -------------------
__device__ float g_h[2][kB * kH];               // ping-pong hidden state (sorted pos)
__device__ float g_pre[(size_t)kT * kB * kH];   // pre[t][pos][n] = x@Wx^T + b
__device__ int g_order[kB];                     // sorted pos -> original batch idx
__device__ int g_lens[kB];                      // length per sorted pos
__device__ int g_count[kT];                     // c_t = #{L > t}, non-increasing

// ---------------------------------------------------------------------------
__global__ void init_kernel() {
  int i = blockIdx.x * blockDim.x + threadIdx.x;
  if (i < kB * kH) { g_h[0][i] = 0.0f; g_h[1][i] = 0.0f; }
}

// Counting sort of batches by seq_length (descending). Handles int64 or int32.
__global__ void sort_kernel(const void* __restrict__ seq_raw) {
  __shared__ int hist[kT + 2];
  __shared__ int off[kT + 2];
  __shared__ int is64;
  int tid = threadIdx.x;  // 256 threads
  hist[tid] = 0;
  if (tid == 0) {
    hist[kT] = 0; hist[kT + 1] = 0;
    const int* v = (const int*)seq_raw;
    int f = 1;
    for (int i = 0; i < 32; ++i)
      if (v[2 * i + 1] != 0) { f = 0; break; }
    is64 = f;
  }
  __syncthreads();
  long long Lv = is64 ? ((const long long*)seq_raw)[tid]
                      : (long long)((const int*)seq_raw)[tid];
  int L = (int)Lv;
  if (L < 0) L = 0;
  if (L > kT) L = kT;
  atomicAdd(&hist[L], 1);
  __syncthreads();
  if (tid == 0) {
    int run = 0;
    for (int t = kT; t >= 0; --t) {
      run += hist[t + 1];
      if (t < kT) g_count[t] = run;  // #{L > t}
      off[t] = run;                  // start of the L == t group
    }
    off[kT + 1] = 0;
  }
  __syncthreads();
  int pos = atomicAdd(&off[L], 1);
  g_order[pos] = tid;
  g_lens[pos] = L;
}

// ---------------------------------------------------------------------------
// Phase A (fully parallel): pre[t][pos][n] = x[order[pos], t] @ Wx_t^T + b_t[n]
__global__ __launch_bounds__(256) void preA_kernel(const float* __restrict__ x,
                                                   const float* __restrict__ Wx,
                                                   const float* __restrict__ bias) {
  __shared__ float As[2][16][68];
  __shared__ float Bs[2][16][68];
  __shared__ int rowB[64];

  const int t = blockIdx.z;
  const int rowBase = blockIdx.x * 64;
  const int colBase = blockIdx.y * 64;
  const int c = g_count[t];
  if (rowBase >= c) return;  // tile fully masked: pre never read

  const int tid = threadIdx.x;
  if (tid < 64) rowB[tid] = g_order[rowBase + tid];
  __syncthreads();

  const int lr = tid >> 2;       // 0..63
  const int lk = (tid & 3) * 4;  // k offset 0,4,8,12
  const float* __restrict__ arow = x + ((size_t)rowB[lr] * kT + t) * kI;
  const float* __restrict__ brow = Wx + ((size_t)t * kH + colBase + lr) * kI;

  const int tx = tid & 15;
  const int ty = tid >> 4;

  unsigned long long acc[4][2];
#pragma unroll
  for (int m = 0; m < 4; ++m) { acc[m][0] = 0ull; acc[m][1] = 0ull; }

  float4 av = *(const float4*)(arow + lk);
  float4 bv = *(const float4*)(brow + lk);
  As[0][lk + 0][lr] = av.x; As[0][lk + 1][lr] = av.y;
  As[0][lk + 2][lr] = av.z; As[0][lk + 3][lr] = av.w;
  Bs[0][lk + 0][lr] = bv.x; Bs[0][lk + 1][lr] = bv.y;
  Bs[0][lk + 2][lr] = bv.z; Bs[0][lk + 3][lr] = bv.w;
  __syncthreads();

  const int nChunks = kI / 16;  // 32
  for (int ci = 0; ci < nChunks; ++ci) {
    int cur = ci & 1;
    if (ci + 1 < nChunks) {
      int k0 = (ci + 1) * 16;
      av = *(const float4*)(arow + k0 + lk);
      bv = *(const float4*)(brow + k0 + lk);
    }
#pragma unroll
    for (int kk = 0; kk < 16; ++kk) {
      float4 a4 = *(const float4*)&As[cur][kk][ty * 4];
      unsigned long long b0 = *(const unsigned long long*)&Bs[cur][kk][tx * 4];
      unsigned long long b1 = *(const unsigned long long*)&Bs[cur][kk][tx * 4 + 2];
      unsigned long long a0 = pack2(a4.x, a4.x);
      unsigned long long a1 = pack2(a4.y, a4.y);
      unsigned long long a2 = pack2(a4.z, a4.z);
      unsigned long long a3 = pack2(a4.w, a4.w);
      fma2(acc[0][0], a0, b0); fma2(acc[0][1], a0, b1);
      fma2(acc[1][0], a1, b0); fma2(acc[1][1], a1, b1);
      fma2(acc[2][0], a2, b0); fma2(acc[2][1], a2, b1);
      fma2(acc[3][0], a3, b0); fma2(acc[3][1], a3, b1);
    }
    if (ci + 1 < nChunks) {
      int nxt = cur ^ 1;
      As[nxt][lk + 0][lr] = av.x; As[nxt][lk + 1][lr] = av.y;
      As[nxt][lk + 2][lr] = av.z; As[nxt][lk + 3][lr] = av.w;
      Bs[nxt][lk + 0][lr] = bv.x; Bs[nxt][lk + 1][lr] = bv.y;
      Bs[nxt][lk + 2][lr] = bv.z; Bs[nxt][lk + 3][lr] = bv.w;
    }
    __syncthreads();
  }

  const float* __restrict__ bptr = bias + (size_t)t * kH + colBase + tx * 4;
  float4 b4 = *(const float4*)bptr;
#pragma unroll
  for (int m = 0; m < 4; ++m) {
    int row = rowBase + ty * 4 + m;
    float2 lo = unpack2(acc[m][0]);
    float2 hi = unpack2(acc[m][1]);
    float4 o;
    o.x = lo.x + b4.x; o.y = lo.y + b4.y; o.z = hi.x + b4.z; o.w = hi.y + b4.w;
    *(float4*)(g_pre + ((size_t)t * kB + row) * kH + colBase + tx * 4) = o;
  }
}

// ---------------------------------------------------------------------------
// Phase B step t: rows pos < c_t: h_out = tanh(pre[t][pos] + h_in[pos] @ Wh_t^T)
// Tile 16(pos) x 64(n). 8 warps = 8 K-groups of 128 each, TK=8, double-buffered.
// Each warp: 4x8 microtile (32 fp32 outputs in 16 u64 accumulators).
__global__ __launch_bounds__(256, 2) void step_kernel(int t, const float* __restrict__ Wh) {
  __shared__ __align__(16) float As[8][2][8][20];   // [grp][buf][k][m]
  __shared__ __align__(16) float Bs[8][2][8][68];   // [grp][buf][k][n]  (4352B/grp)

  const int c = g_count[t];
  const int rowBase = blockIdx.x * 16;
  if (rowBase >= c) return;
  const int colBase = blockIdx.y * 64;

  const int pp = t & 1;
  const float* __restrict__ hIn = g_h[pp];
  float* __restrict__ hOut = g_h[pp ^ 1];

  const int tid = threadIdx.x;
  const int g = tid >> 5;      // warp = K-group 0..7
  const int lt = tid & 31;
  const int kStart = g * 128;

  // loader indices (within group)
  const int laRow = lt >> 1;          // 0..15
  const int laK = (lt & 1) * 4;       // 0 or 4
  // B: cols lt and lt+32, 8 k each

  // compute indices
  const int ry = lt >> 3;   // 0..3 -> rows ry*4..ry*4+3
  const int cx = lt & 7;    // 0..7 -> cols cx*8..cx*8+7

  const float* __restrict__ aPtr =
      hIn + (size_t)(rowBase + laRow) * kH + kStart + laK;
  const float* __restrict__ bPtr0 =
      Wh + ((size_t)t * kH + colBase + lt) * kH + kStart;
  const float* __restrict__ bPtr1 = bPtr0 + (size_t)32 * kH;

  // ---- L2 prefetch for step t+1 (deduplicated across the grid) ----
  if (t + 1 < kT) {
    if (blockIdx.x == 0) {
      const float* nf = Wh + ((size_t)(t + 1) * kH + colBase) * kH;
      for (int i = tid; i < 2048; i += 256) {
        int r = i >> 5;
        int o = (i & 31) * 32;
        pf_l2(nf + (size_t)r * kH + o);
      }
    }
    if (blockIdx.y == 0) {
      const float* pp2 = g_pre + ((size_t)(t + 1) * kB + rowBase) * kH;
      for (int i = tid; i < 512; i += 256) {
        int r = i >> 5;
        int o = (i & 31) * 32;
        pf_l2(pp2 + (size_t)r * kH + o);
      }
    }
  }

  unsigned long long acc[4][4];
#pragma unroll
  for (int m = 0; m < 4; ++m)
#pragma unroll
    for (int j = 0; j < 4; ++j) acc[m][j] = 0ull;

  // preload chunk 0 -> buf 0
  {
    float4 a4 = *(const float4*)(aPtr);
    float4 b00 = *(const float4*)(bPtr0);
    float4 b01 = *(const float4*)(bPtr0 + 4);
    float4 b10 = *(const float4*)(bPtr1);
    float4 b11 = *(const float4*)(bPtr1 + 4);
    As[g][0][laK + 0][laRow] = a4.x; As[g][0][laK + 1][laRow] = a4.y;
    As[g][0][laK + 2][laRow] = a4.z; As[g][0][laK + 3][laRow] = a4.w;
    Bs[g][0][0][lt] = b00.x; Bs[g][0][1][lt] = b00.y;
    Bs[g][0][2][lt] = b00.z; Bs[g][0][3][lt] = b00.w;
    Bs[g][0][4][lt] = b01.x; Bs[g][0][5][lt] = b01.y;
    Bs[g][0][6][lt] = b01.z; Bs[g][0][7][lt] = b01.w;
    Bs[g][0][0][lt + 32] = b10.x; Bs[g][0][1][lt + 32] = b10.y;
    Bs[g][0][2][lt + 32] = b10.z; Bs[g][0][3][lt + 32] = b10.w;
    Bs[g][0][4][lt + 32] = b11.x; Bs[g][0][5][lt + 32] = b11.y;
    Bs[g][0][6][lt + 32] = b11.z; Bs[g][0][7][lt + 32] = b11.w;
  }
  __syncthreads();

  const int nChunks = 16;  // 128 K per group / TK=8
  float4 a4, b00, b01, b10, b11;
  for (int ci = 0; ci < nChunks; ++ci) {
    const int cur = ci & 1;
    if (ci + 1 < nChunks) {
      const int k0 = (ci + 1) * 8;
      a4 = *(const float4*)(aPtr + k0);
      b00 = *(const float4*)(bPtr0 + k0);
      b01 = *(const float4*)(bPtr0 + k0 + 4);
      b10 = *(const float4*)(bPtr1 + k0);
      b11 = *(const float4*)(bPtr1 + k0 + 4);
    }
#pragma unroll
    for (int kk = 0; kk < 8; ++kk) {
      float4 av = *(const float4*)&As[g][cur][kk][ry * 4];
      const unsigned long long* bp =
          (const unsigned long long*)&Bs[g][cur][kk][cx * 8];
      unsigned long long bb0 = bp[0];
      unsigned long long bb1 = bp[1];
      unsigned long long bb2 = bp[2];
      unsigned long long bb3 = bp[3];
      unsigned long long am;
      am = pack2(av.x, av.x);
      fma2(acc[0][0], am, bb0); fma2(acc[0][1], am, bb1);
      fma2(acc[0][2], am, bb2); fma2(acc[0][3], am, bb3);
      am = pack2(av.y, av.y);
      fma2(acc[1][0], am, bb0); fma2(acc[1][1], am, bb1);
      fma2(acc[1][2], am, bb2); fma2(acc[1][3], am, bb3);
      am = pack2(av.z, av.z);
      fma2(acc[2][0], am, bb0); fma2(acc[2][1], am, bb1);
      fma2(acc[2][2], am, bb2); fma2(acc[2][3], am, bb3);
      am = pack2(av.w, av.w);
      fma2(acc[3][0], am, bb0); fma2(acc[3][1], am, bb1);
      fma2(acc[3][2], am, bb2); fma2(acc[3][3], am, bb3);
    }
    if (ci + 1 < nChunks) {
      const int nxt = cur ^ 1;
      As[g][nxt][laK + 0][laRow] = a4.x; As[g][nxt][laK + 1][laRow] = a4.y;
      As[g][nxt][laK + 2][laRow] = a4.z; As[g][nxt][laK + 3][laRow] = a4.w;
      Bs[g][nxt][0][lt] = b00.x; Bs[g][nxt][1][lt] = b00.y;
      Bs[g][nxt][2][lt] = b00.z; Bs[g][nxt][3][lt] = b00.w;
      Bs[g][nxt][4][lt] = b01.x; Bs[g][nxt][5][lt] = b01.y;
      Bs[g][nxt][6][lt] = b01.z; Bs[g][nxt][7][lt] = b01.w;
      Bs[g][nxt][0][lt + 32] = b10.x; Bs[g][nxt][1][lt + 32] = b10.y;
      Bs[g][nxt][2][lt + 32] = b10.z; Bs[g][nxt][3][lt + 32] = b10.w;
      Bs[g][nxt][4][lt + 32] = b11.x; Bs[g][nxt][5][lt + 32] = b11.y;
      Bs[g][nxt][6][lt + 32] = b11.z; Bs[g][nxt][7][lt + 32] = b11.w;
    }
    __syncthreads();
  }

  // ---- deposit partials into this group's own B buffer (now dead) ----
  float* Redg = &Bs[g][0][0][0];  // 16 rows x 68 floats (4352B fits exactly)
#pragma unroll
  for (int m = 0; m < 4; ++m) {
    int row = ry * 4 + m;
#pragma unroll
    for (int j = 0; j < 4; ++j) {
      *(unsigned long long*)&Redg[row * 68 + cx * 8 + j * 2] = acc[m][j];
    }
  }
  __syncthreads();

  // ---- cross-group reduce + pre + tanh + store (256 threads, 4 outputs) ----
  {
    const int row = tid >> 4;        // 0..15
    const int col = (tid & 15) * 4;  // 0..60
    const int pos = rowBase + row;
    if (pos < c) {
      float4 s = {0.f, 0.f, 0.f, 0.f};
#pragma unroll
      for (int gg = 0; gg < 8; ++gg) {
        const float* R = &Bs[gg][0][0][0];
        float4 v = *(const float4*)&R[row * 68 + col];
        s.x += v.x; s.y += v.y; s.z += v.z; s.w += v.w;
      }
      const float* pr = g_pre + ((size_t)t * kB + pos) * kH + colBase + col;
      float4 p4 = *(const float4*)pr;
      float4 o;
      o.x = tanhf(s.x + p4.x);
      o.y = tanhf(s.y + p4.y);
      o.z = tanhf(s.z + p4.z);
      o.w = tanhf(s.w + p4.w);
      *(float4*)(hOut + (size_t)pos * kH + colBase + col) = o;
    }
  }
}

// ---------------------------------------------------------------------------
// out[order[pos]] = h_final[pos] . W_out + b_out  (final h lives in buffer L&1)
__global__ void out_kernel(const float* __restrict__ Wout,
                           const float* __restrict__ bout,
                           float* __restrict__ out) {
  int pos = blockIdx.x;
  int L = g_lens[pos];
  const float* h = g_h[L & 1] + (size_t)pos * kH;
  float s = 0.0f;
  for (int i = threadIdx.x; i < kH; i += blockDim.x) s += h[i] * Wout[i];
#pragma unroll
  for (int o = 16; o > 0; o >>= 1) s += __shfl_down_sync(0xffffffffu, s, o);
  __shared__ float red[4];
  if ((threadIdx.x & 31) == 0) red[threadIdx.x >> 5] = s;
  __syncthreads();
  if (threadIdx.x == 0) {
    float tot = red[0] + red[1] + red[2] + red[3];
    out[g_order[pos]] = tot + bout[0];
  }
}

// ---------------------------------------------------------------------------
extern "C" void kernel_launch(void* const* d_in, const int* in_sizes, int n_in,
                              void* d_out, int out_size) {
  const float* x = (const float*)d_in[0];
  const void* seq = d_in[1];
  const float* Wx = (const float*)d_in[2];
  const float* Wh = (const float*)d_in[3];
  const float* bias = (const float*)d_in[4];
  const float* Wout = (const float*)d_in[5];
  const float* bout = (const float*)d_in[6];
  float* out = (float*)d_out;

  init_kernel<<<(kB * kH + 255) / 256, 256>>>();
  sort_kernel<<<1, kB>>>(seq);

  // Phase A: all (t, row-tile, col-tile) GEMMs in one launch
  preA_kernel<<<dim3(kB / 64, kH / 64, kT), 256>>>(x, Wx, bias);

  // Phase B: sequential recurrence, L2-prefetching one step ahead
  for (int t = 0; t < kT; ++t) {
    step_kernel<<<dim3(16, 16), 256>>>(t, Wh);
  }
  out_kernel<<<kB, 128>>>(Wout, bout, out);
}

// round 11
// speedup vs baseline: 1.1007x; 1.1007x over previous
#include <cuda_runtime.h>
#include <math.h>

namespace {
constexpr int kB = 256;   // batch
constexpr int kT = 256;   // timesteps
constexpr int kI = 512;   // input dim
constexpr int kH = 1024;  // hidden dim
}

// ---------------- packed f32x2 helpers (SASS FFMA2 path) --------------------
__device__ __forceinline__ unsigned long long pack2(float x, float y) {
  unsigned long long r;
  asm("mov.b64 %0, {%1, %2};" : "=l"(r) : "f"(x), "f"(y));
  return r;
}
__device__ __forceinline__ void fma2(unsigned long long& d, unsigned long long a,
                                     unsigned long long b) {
  asm("fma.rn.f32x2 %0, %1, %2, %0;" : "+l"(d) : "l"(a), "l"(b));
}
__device__ __forceinline__ float2 unpack2(unsigned long long v) {
  float2 r;
  asm("mov.b64 {%0, %1}, %2;" : "=f"(r.x), "=f"(r.y) : "l"(v));
  return r;
}
__device__ __forceinline__ void pf_l2(const float* p) {
  asm volatile("prefetch.global.L2 [%0];" ::"l"(p));
}

// ---------------- device scratch (no allocations allowed) -------------------
__device__ float g_h[2][kB * kH];               // ping-pong hidden state (sorted pos)
__device__ float g_pre[(size_t)kT * kB * kH];   // pre[t][pos][n] = x@Wx^T + b
__device__ float g_whT[(size_t)kT * kH * kH];   // WhT[t][k][n] = Wh[t][n][k]  (1GB)
__device__ int g_order[kB];                     // sorted pos -> original batch idx
__device__ int g_lens[kB];                      // length per sorted pos
__device__ int g_count[kT];                     // c_t = #{L > t}, non-increasing

// ---------------------------------------------------------------------------
__global__ void init_kernel() {
  int i = blockIdx.x * blockDim.x + threadIdx.x;
  if (i < kB * kH) { g_h[0][i] = 0.0f; g_h[1][i] = 0.0f; }
}

// Counting sort of batches by seq_length (descending). Handles int64 or int32.
__global__ void sort_kernel(const void* __restrict__ seq_raw) {
  __shared__ int hist[kT + 2];
  __shared__ int off[kT + 2];
  __shared__ int is64;
  int tid = threadIdx.x;  // 256 threads
  hist[tid] = 0;
  if (tid == 0) {
    hist[kT] = 0; hist[kT + 1] = 0;
    const int* v = (const int*)seq_raw;
    int f = 1;
    for (int i = 0; i < 32; ++i)
      if (v[2 * i + 1] != 0) { f = 0; break; }
    is64 = f;
  }
  __syncthreads();
  long long Lv = is64 ? ((const long long*)seq_raw)[tid]
                      : (long long)((const int*)seq_raw)[tid];
  int L = (int)Lv;
  if (L < 0) L = 0;
  if (L > kT) L = kT;
  atomicAdd(&hist[L], 1);
  __syncthreads();
  if (tid == 0) {
    int run = 0;
    for (int t = kT; t >= 0; --t) {
      run += hist[t + 1];
      if (t < kT) g_count[t] = run;  // #{L > t}
      off[t] = run;                  // start of the L == t group
    }
    off[kT + 1] = 0;
  }
  __syncthreads();
  int pos = atomicAdd(&off[L], 1);
  g_order[pos] = tid;
  g_lens[pos] = L;
}

// ---------------------------------------------------------------------------
// One-time weight transpose: WhT[t][k][n] = Wh[t][n][k]. Coalesced both sides.
__global__ void transpose_kernel(const float* __restrict__ Wh) {
  __shared__ float tile[32][33];
  const int t = blockIdx.z;
  const int n0 = blockIdx.x * 32;  // h_out block
  const int k0 = blockIdx.y * 32;  // h_in block
  const int tx = threadIdx.x;      // 0..31
  const int ty = threadIdx.y;      // 0..7

  const float* src = Wh + ((size_t)t * kH + n0) * kH + k0;
  for (int i = ty; i < 32; i += 8)
    tile[i][tx] = src[(size_t)i * kH + tx];  // tile[a][b] = Wh[n0+a][k0+b]
  __syncthreads();
  float* dst = g_whT + ((size_t)t * kH + k0) * kH + n0;
  for (int i = ty; i < 32; i += 8)
    dst[(size_t)i * kH + tx] = tile[tx][i];  // WhT[k0+i][n0+tx] = Wh[n0+tx][k0+i]
}

// ---------------------------------------------------------------------------
// Phase A (fully parallel): pre[t][pos][n] = x[order[pos], t] @ Wx_t^T + b_t[n]
__global__ __launch_bounds__(256) void preA_kernel(const float* __restrict__ x,
                                                   const float* __restrict__ Wx,
                                                   const float* __restrict__ bias) {
  __shared__ float As[2][16][68];
  __shared__ float Bs[2][16][68];
  __shared__ int rowB[64];

  const int t = blockIdx.z;
  const int rowBase = blockIdx.x * 64;
  const int colBase = blockIdx.y * 64;
  const int c = g_count[t];
  if (rowBase >= c) return;  // tile fully masked: pre never read

  const int tid = threadIdx.x;
  if (tid < 64) rowB[tid] = g_order[rowBase + tid];
  __syncthreads();

  const int lr = tid >> 2;       // 0..63
  const int lk = (tid & 3) * 4;  // k offset 0,4,8,12
  const float* __restrict__ arow = x + ((size_t)rowB[lr] * kT + t) * kI;
  const float* __restrict__ brow = Wx + ((size_t)t * kH + colBase + lr) * kI;

  const int tx = tid & 15;
  const int ty = tid >> 4;

  unsigned long long acc[4][2];
#pragma unroll
  for (int m = 0; m < 4; ++m) { acc[m][0] = 0ull; acc[m][1] = 0ull; }

  float4 av = *(const float4*)(arow + lk);
  float4 bv = *(const float4*)(brow + lk);
  As[0][lk + 0][lr] = av.x; As[0][lk + 1][lr] = av.y;
  As[0][lk + 2][lr] = av.z; As[0][lk + 3][lr] = av.w;
  Bs[0][lk + 0][lr] = bv.x; Bs[0][lk + 1][lr] = bv.y;
  Bs[0][lk + 2][lr] = bv.z; Bs[0][lk + 3][lr] = bv.w;
  __syncthreads();

  const int nChunks = kI / 16;  // 32
  for (int ci = 0; ci < nChunks; ++ci) {
    int cur = ci & 1;
    if (ci + 1 < nChunks) {
      int k0 = (ci + 1) * 16;
      av = *(const float4*)(arow + k0 + lk);
      bv = *(const float4*)(brow + k0 + lk);
    }
#pragma unroll
    for (int kk = 0; kk < 16; ++kk) {
      float4 a4 = *(const float4*)&As[cur][kk][ty * 4];
      unsigned long long b0 = *(const unsigned long long*)&Bs[cur][kk][tx * 4];
      unsigned long long b1 = *(const unsigned long long*)&Bs[cur][kk][tx * 4 + 2];
      unsigned long long a0 = pack2(a4.x, a4.x);
      unsigned long long a1 = pack2(a4.y, a4.y);
      unsigned long long a2 = pack2(a4.z, a4.z);
      unsigned long long a3 = pack2(a4.w, a4.w);
      fma2(acc[0][0], a0, b0); fma2(acc[0][1], a0, b1);
      fma2(acc[1][0], a1, b0); fma2(acc[1][1], a1, b1);
      fma2(acc[2][0], a2, b0); fma2(acc[2][1], a2, b1);
      fma2(acc[3][0], a3, b0); fma2(acc[3][1], a3, b1);
    }
    if (ci + 1 < nChunks) {
      int nxt = cur ^ 1;
      As[nxt][lk + 0][lr] = av.x; As[nxt][lk + 1][lr] = av.y;
      As[nxt][lk + 2][lr] = av.z; As[nxt][lk + 3][lr] = av.w;
      Bs[nxt][lk + 0][lr] = bv.x; Bs[nxt][lk + 1][lr] = bv.y;
      Bs[nxt][lk + 2][lr] = bv.z; Bs[nxt][lk + 3][lr] = bv.w;
    }
    __syncthreads();
  }

  const float* __restrict__ bptr = bias + (size_t)t * kH + colBase + tx * 4;
  float4 b4 = *(const float4*)bptr;
#pragma unroll
  for (int m = 0; m < 4; ++m) {
    int row = rowBase + ty * 4 + m;
    float2 lo = unpack2(acc[m][0]);
    float2 hi = unpack2(acc[m][1]);
    float4 o;
    o.x = lo.x + b4.x; o.y = lo.y + b4.y; o.z = hi.x + b4.z; o.w = hi.y + b4.w;
    *(float4*)(g_pre + ((size_t)t * kB + row) * kH + colBase + tx * 4) = o;
  }
}

// ---------------------------------------------------------------------------
// Phase B step t: rows pos < c_t: h_out = tanh(pre[t][pos] + h_in[pos] @ Wh_t^T)
// Tile 16(pos) x 64(n). 8 warps = 8 K-groups of 128 each, TK=8, double-buffered.
// Weights read from K-major WhT -> all global loads coalesced.
__global__ __launch_bounds__(256, 2) void step_kernel(int t) {
  __shared__ __align__(16) float As[8][2][8][20];   // [grp][buf][k][m]
  __shared__ __align__(16) float Bs[8][2][8][68];   // [grp][buf][k][n]

  const int c = g_count[t];
  const int rowBase = blockIdx.x * 16;
  if (rowBase >= c) return;
  const int colBase = blockIdx.y * 64;

  const int pp = t & 1;
  const float* __restrict__ hIn = g_h[pp];
  float* __restrict__ hOut = g_h[pp ^ 1];

  const int tid = threadIdx.x;
  const int g = tid >> 5;      // warp = K-group 0..7
  const int lt = tid & 31;
  const int kStart = g * 128;

  // A loader: 2 lanes per row, float4 each -> 16 rows x 8 k
  const int laRow = lt >> 1;          // 0..15
  const int laK = (lt & 1) * 4;       // 0 or 4
  // B loader: 4 lanes per k-row, 16 consecutive n each (4x float4)
  const int lbK = lt >> 2;            // 0..7 (k within chunk)
  const int lbN = (lt & 3) * 16;      // 0,16,32,48

  // compute indices
  const int ry = lt >> 3;   // 0..3 -> rows ry*4..ry*4+3
  const int cx = lt & 7;    // 0..7 -> cols cx*8..cx*8+7

  const float* __restrict__ aPtr =
      hIn + (size_t)(rowBase + laRow) * kH + kStart + laK;
  const float* __restrict__ bPtr =
      g_whT + ((size_t)t * kH + kStart + lbK) * kH + colBase + lbN;

  // ---- L2 prefetch for step t+1 (deduplicated across the grid) ----
  if (t + 1 < kT) {
    if (blockIdx.x == 0) {
      // WhT_{t+1} slab for this col tile: 1024 k-rows x 256B = 2048 lines
      const float* nf = g_whT + ((size_t)(t + 1) * kH) * kH + colBase;
      for (int i = tid; i < 2048; i += 256) {
        int k = i >> 1;
        int o = (i & 1) * 32;
        pf_l2(nf + (size_t)k * kH + o);
      }
    }
    if (blockIdx.y == 0) {
      const float* pp2 = g_pre + ((size_t)(t + 1) * kB + rowBase) * kH;
      for (int i = tid; i < 512; i += 256) {
        int r = i >> 5;
        int o = (i & 31) * 32;
        pf_l2(pp2 + (size_t)r * kH + o);
      }
    }
  }

  unsigned long long acc[4][4];
#pragma unroll
  for (int m = 0; m < 4; ++m)
#pragma unroll
    for (int j = 0; j < 4; ++j) acc[m][j] = 0ull;

  // preload chunk 0 -> buf 0
  {
    float4 a4 = *(const float4*)(aPtr);
    float4 b0 = *(const float4*)(bPtr);
    float4 b1 = *(const float4*)(bPtr + 4);
    float4 b2 = *(const float4*)(bPtr + 8);
    float4 b3 = *(const float4*)(bPtr + 12);
    As[g][0][laK + 0][laRow] = a4.x; As[g][0][laK + 1][laRow] = a4.y;
    As[g][0][laK + 2][laRow] = a4.z; As[g][0][laK + 3][laRow] = a4.w;
    *(float4*)&Bs[g][0][lbK][lbN + 0] = b0;
    *(float4*)&Bs[g][0][lbK][lbN + 4] = b1;
    *(float4*)&Bs[g][0][lbK][lbN + 8] = b2;
    *(float4*)&Bs[g][0][lbK][lbN + 12] = b3;
  }
  __syncthreads();

  const int nChunks = 16;  // 128 K per group / TK=8
  float4 a4, b0, b1, b2, b3;
  for (int ci = 0; ci < nChunks; ++ci) {
    const int cur = ci & 1;
    if (ci + 1 < nChunks) {
      const int k0 = (ci + 1) * 8;
      a4 = *(const float4*)(aPtr + k0);
      const float* bp = bPtr + (size_t)k0 * kH;
      b0 = *(const float4*)(bp);
      b1 = *(const float4*)(bp + 4);
      b2 = *(const float4*)(bp + 8);
      b3 = *(const float4*)(bp + 12);
    }
#pragma unroll
    for (int kk = 0; kk < 8; ++kk) {
      float4 av = *(const float4*)&As[g][cur][kk][ry * 4];
      const unsigned long long* bp =
          (const unsigned long long*)&Bs[g][cur][kk][cx * 8];
      unsigned long long bb0 = bp[0];
      unsigned long long bb1 = bp[1];
      unsigned long long bb2 = bp[2];
      unsigned long long bb3 = bp[3];
      unsigned long long am;
      am = pack2(av.x, av.x);
      fma2(acc[0][0], am, bb0); fma2(acc[0][1], am, bb1);
      fma2(acc[0][2], am, bb2); fma2(acc[0][3], am, bb3);
      am = pack2(av.y, av.y);
      fma2(acc[1][0], am, bb0); fma2(acc[1][1], am, bb1);
      fma2(acc[1][2], am, bb2); fma2(acc[1][3], am, bb3);
      am = pack2(av.z, av.z);
      fma2(acc[2][0], am, bb0); fma2(acc[2][1], am, bb1);
      fma2(acc[2][2], am, bb2); fma2(acc[2][3], am, bb3);
      am = pack2(av.w, av.w);
      fma2(acc[3][0], am, bb0); fma2(acc[3][1], am, bb1);
      fma2(acc[3][2], am, bb2); fma2(acc[3][3], am, bb3);
    }
    if (ci + 1 < nChunks) {
      const int nxt = cur ^ 1;
      As[g][nxt][laK + 0][laRow] = a4.x; As[g][nxt][laK + 1][laRow] = a4.y;
      As[g][nxt][laK + 2][laRow] = a4.z; As[g][nxt][laK + 3][laRow] = a4.w;
      *(float4*)&Bs[g][nxt][lbK][lbN + 0] = b0;
      *(float4*)&Bs[g][nxt][lbK][lbN + 4] = b1;
      *(float4*)&Bs[g][nxt][lbK][lbN + 8] = b2;
      *(float4*)&Bs[g][nxt][lbK][lbN + 12] = b3;
    }
    __syncthreads();
  }

  // ---- deposit partials into this group's own B buffer (now dead) ----
  float* Redg = &Bs[g][0][0][0];  // 16 rows x 68 floats (4352B fits exactly)
#pragma unroll
  for (int m = 0; m < 4; ++m) {
    int row = ry * 4 + m;
#pragma unroll
    for (int j = 0; j < 4; ++j) {
      *(unsigned long long*)&Redg[row * 68 + cx * 8 + j * 2] = acc[m][j];
    }
  }
  __syncthreads();

  // ---- cross-group reduce + pre + tanh + store (256 threads, 4 outputs) ----
  {
    const int row = tid >> 4;        // 0..15
    const int col = (tid & 15) * 4;  // 0..60
    const int pos = rowBase + row;
    if (pos < c) {
      float4 s = {0.f, 0.f, 0.f, 0.f};
#pragma unroll
      for (int gg = 0; gg < 8; ++gg) {
        const float* R = &Bs[gg][0][0][0];
        float4 v = *(const float4*)&R[row * 68 + col];
        s.x += v.x; s.y += v.y; s.z += v.z; s.w += v.w;
      }
      const float* pr = g_pre + ((size_t)t * kB + pos) * kH + colBase + col;
      float4 p4 = *(const float4*)pr;
      float4 o;
      o.x = tanhf(s.x + p4.x);
      o.y = tanhf(s.y + p4.y);
      o.z = tanhf(s.z + p4.z);
      o.w = tanhf(s.w + p4.w);
      *(float4*)(hOut + (size_t)pos * kH + colBase + col) = o;
    }
  }
}

// ---------------------------------------------------------------------------
// out[order[pos]] = h_final[pos] . W_out + b_out  (final h lives in buffer L&1)
__global__ void out_kernel(const float* __restrict__ Wout,
                           const float* __restrict__ bout,
                           float* __restrict__ out) {
  int pos = blockIdx.x;
  int L = g_lens[pos];
  const float* h = g_h[L & 1] + (size_t)pos * kH;
  float s = 0.0f;
  for (int i = threadIdx.x; i < kH; i += blockDim.x) s += h[i] * Wout[i];
#pragma unroll
  for (int o = 16; o > 0; o >>= 1) s += __shfl_down_sync(0xffffffffu, s, o);
  __shared__ float red[4];
  if ((threadIdx.x & 31) == 0) red[threadIdx.x >> 5] = s;
  __syncthreads();
  if (threadIdx.x == 0) {
    float tot = red[0] + red[1] + red[2] + red[3];
    out[g_order[pos]] = tot + bout[0];
  }
}

// ---------------------------------------------------------------------------
extern "C" void kernel_launch(void* const* d_in, const int* in_sizes, int n_in,
                              void* d_out, int out_size) {
  const float* x = (const float*)d_in[0];
  const void* seq = d_in[1];
  const float* Wx = (const float*)d_in[2];
  const float* Wh = (const float*)d_in[3];
  const float* bias = (const float*)d_in[4];
  const float* Wout = (const float*)d_in[5];
  const float* bout = (const float*)d_in[6];
  float* out = (float*)d_out;

  init_kernel<<<(kB * kH + 255) / 256, 256>>>();
  sort_kernel<<<1, kB>>>(seq);

  // One-time: transpose Wh into K-major WhT
  transpose_kernel<<<dim3(kH / 32, kH / 32, kT), dim3(32, 8)>>>(Wh);

  // Phase A: all (t, row-tile, col-tile) GEMMs in one launch
  preA_kernel<<<dim3(kB / 64, kH / 64, kT), 256>>>(x, Wx, bias);

  // Phase B: sequential recurrence, L2-prefetching one step ahead
  for (int t = 0; t < kT; ++t) {
    step_kernel<<<dim3(16, 16), 256>>>(t);
  }
  out_kernel<<<kB, 128>>>(Wout, bout, out);
}

// round 14
// speedup vs baseline: 1.6585x; 1.5068x over previous
#include <cuda_runtime.h>
#include <cuda_bf16.h>
#include <math.h>
#include <stdint.h>

namespace {
constexpr int kB = 256;   // batch
constexpr int kT = 256;   // timesteps
constexpr int kI = 512;   // input dim
constexpr int kH = 1024;  // hidden dim

constexpr int TM = 32;    // rows (pos) per step CTA
constexpr int TN = 64;    // cols per step CTA
constexpr int TK = 32;    // K per chunk
constexpr int NCH = kH / TK;  // 32 chunks
constexpr int ASTR = 40;  // smem row stride (bf16 elems) -> 80B, conflict-free
}

// ---------------- packed f32x2 helpers (preA scalar GEMM) -------------------
__device__ __forceinline__ unsigned long long pack2(float x, float y) {
  unsigned long long r;
  asm("mov.b64 %0, {%1, %2};" : "=l"(r) : "f"(x), "f"(y));
  return r;
}
__device__ __forceinline__ void fma2(unsigned long long& d, unsigned long long a,
                                     unsigned long long b) {
  asm("fma.rn.f32x2 %0, %1, %2, %0;" : "+l"(d) : "l"(a), "l"(b));
}
__device__ __forceinline__ float2 unpack2(unsigned long long v) {
  float2 r;
  asm("mov.b64 {%0, %1}, %2;" : "=f"(r.x), "=f"(r.y) : "l"(v));
  return r;
}
__device__ __forceinline__ void pf_l2(const void* p) {
  asm volatile("prefetch.global.L2 [%0];" ::"l"(p));
}

// mma.sync m16n8k16 bf16 (baseline sm_80 PTX -> compiles for compute_103)
__device__ __forceinline__ void mma_bf16(float* d, uint32_t a0, uint32_t a1,
                                         uint32_t a2, uint32_t a3, uint32_t b0,
                                         uint32_t b1) {
  asm volatile(
      "mma.sync.aligned.m16n8k16.row.col.f32.bf16.bf16.f32 "
      "{%0,%1,%2,%3}, {%4,%5,%6,%7}, {%8,%9}, {%0,%1,%2,%3};"
      : "+f"(d[0]), "+f"(d[1]), "+f"(d[2]), "+f"(d[3])
      : "r"(a0), "r"(a1), "r"(a2), "r"(a3), "r"(b0), "r"(b1));
}

// ---------------- device scratch (no allocations allowed) -------------------
__device__ float g_hf[2][kB * kH];                     // fp32 h ping-pong
__device__ __nv_bfloat16 g_hh[2][kB * kH];             // h hi
__device__ __nv_bfloat16 g_hl[2][kB * kH];             // h lo
__device__ float g_pre[(size_t)kT * kB * kH];          // x@Wx^T + b
__device__ __nv_bfloat16 g_whh[(size_t)kT * kH * kH];  // Wh hi [t][n][k]
__device__ __nv_bfloat16 g_whl[(size_t)kT * kH * kH];  // Wh lo [t][n][k]
__device__ int g_order[kB];
__device__ int g_lens[kB];
__device__ int g_count[kT];

// ---------------------------------------------------------------------------
__global__ void init_kernel() {
  int i = blockIdx.x * blockDim.x + threadIdx.x;
  if (i < kB * kH) {
    g_hf[0][i] = 0.0f; g_hf[1][i] = 0.0f;
    __nv_bfloat16 z = __float2bfloat16(0.0f);
    g_hh[0][i] = z; g_hh[1][i] = z;
    g_hl[0][i] = z; g_hl[1][i] = z;
  }
}

// Counting sort of batches by seq_length (descending). Handles int64 or int32.
__global__ void sort_kernel(const void* __restrict__ seq_raw) {
  __shared__ int hist[kT + 2];
  __shared__ int off[kT + 2];
  __shared__ int is64;
  int tid = threadIdx.x;
  hist[tid] = 0;
  if (tid == 0) {
    hist[kT] = 0; hist[kT + 1] = 0;
    const int* v = (const int*)seq_raw;
    int f = 1;
    for (int i = 0; i < 32; ++i)
      if (v[2 * i + 1] != 0) { f = 0; break; }
    is64 = f;
  }
  __syncthreads();
  long long Lv = is64 ? ((const long long*)seq_raw)[tid]
                      : (long long)((const int*)seq_raw)[tid];
  int L = (int)Lv;
  if (L < 0) L = 0;
  if (L > kT) L = kT;
  atomicAdd(&hist[L], 1);
  __syncthreads();
  if (tid == 0) {
    int run = 0;
    for (int t = kT; t >= 0; --t) {
      run += hist[t + 1];
      if (t < kT) g_count[t] = run;
      off[t] = run;
    }
    off[kT + 1] = 0;
  }
  __syncthreads();
  int pos = atomicAdd(&off[L], 1);
  g_order[pos] = tid;
  g_lens[pos] = L;
}

// ---------------------------------------------------------------------------
// One-time: split Wh into bf16 hi + lo (same [t][n][k] layout).
__global__ void split_wh(const float* __restrict__ Wh) {
  size_t i = ((size_t)blockIdx.x * blockDim.x + threadIdx.x) * 4;
  const size_t n = (size_t)kT * kH * kH;
  if (i >= n) return;
  float4 w = *(const float4*)(Wh + i);
  __nv_bfloat16 h0 = __float2bfloat16(w.x), h1 = __float2bfloat16(w.y);
  __nv_bfloat16 h2 = __float2bfloat16(w.z), h3 = __float2bfloat16(w.w);
  __nv_bfloat162 hp0; hp0.x = h0; hp0.y = h1;
  __nv_bfloat162 hp1; hp1.x = h2; hp1.y = h3;
  *(__nv_bfloat162*)(g_whh + i) = hp0;
  *(__nv_bfloat162*)(g_whh + i + 2) = hp1;
  __nv_bfloat162 lp0, lp1;
  lp0.x = __float2bfloat16(w.x - __bfloat162float(h0));
  lp0.y = __float2bfloat16(w.y - __bfloat162float(h1));
  lp1.x = __float2bfloat16(w.z - __bfloat162float(h2));
  lp1.y = __float2bfloat16(w.w - __bfloat162float(h3));
  *(__nv_bfloat162*)(g_whl + i) = lp0;
  *(__nv_bfloat162*)(g_whl + i + 2) = lp1;
}

// ---------------------------------------------------------------------------
// Phase A (fully parallel): pre[t][pos][n] = x[order[pos], t] @ Wx_t^T + b_t[n]
__global__ __launch_bounds__(256) void preA_kernel(const float* __restrict__ x,
                                                   const float* __restrict__ Wx,
                                                   const float* __restrict__ bias) {
  __shared__ float As[2][16][68];
  __shared__ float Bs[2][16][68];
  __shared__ int rowB[64];

  const int t = blockIdx.z;
  const int rowBase = blockIdx.x * 64;
  const int colBase = blockIdx.y * 64;
  const int c = g_count[t];
  if (rowBase >= c) return;

  const int tid = threadIdx.x;
  if (tid < 64) rowB[tid] = g_order[rowBase + tid];
  __syncthreads();

  const int lr = tid >> 2;
  const int lk = (tid & 3) * 4;
  const float* __restrict__ arow = x + ((size_t)rowB[lr] * kT + t) * kI;
  const float* __restrict__ brow = Wx + ((size_t)t * kH + colBase + lr) * kI;

  const int tx = tid & 15;
  const int ty = tid >> 4;

  unsigned long long acc[4][2];
#pragma unroll
  for (int m = 0; m < 4; ++m) { acc[m][0] = 0ull; acc[m][1] = 0ull; }

  float4 av = *(const float4*)(arow + lk);
  float4 bv = *(const float4*)(brow + lk);
  As[0][lk + 0][lr] = av.x; As[0][lk + 1][lr] = av.y;
  As[0][lk + 2][lr] = av.z; As[0][lk + 3][lr] = av.w;
  Bs[0][lk + 0][lr] = bv.x; Bs[0][lk + 1][lr] = bv.y;
  Bs[0][lk + 2][lr] = bv.z; Bs[0][lk + 3][lr] = bv.w;
  __syncthreads();

  const int nChunks = kI / 16;
  for (int ci = 0; ci < nChunks; ++ci) {
    int cur = ci & 1;
    if (ci + 1 < nChunks) {
      int k0 = (ci + 1) * 16;
      av = *(const float4*)(arow + k0 + lk);
      bv = *(const float4*)(brow + k0 + lk);
    }
#pragma unroll
    for (int kk = 0; kk < 16; ++kk) {
      float4 a4 = *(const float4*)&As[cur][kk][ty * 4];
      unsigned long long b0 = *(const unsigned long long*)&Bs[cur][kk][tx * 4];
      unsigned long long b1 = *(const unsigned long long*)&Bs[cur][kk][tx * 4 + 2];
      unsigned long long a0 = pack2(a4.x, a4.x);
      unsigned long long a1 = pack2(a4.y, a4.y);
      unsigned long long a2 = pack2(a4.z, a4.z);
      unsigned long long a3 = pack2(a4.w, a4.w);
      fma2(acc[0][0], a0, b0); fma2(acc[0][1], a0, b1);
      fma2(acc[1][0], a1, b0); fma2(acc[1][1], a1, b1);
      fma2(acc[2][0], a2, b0); fma2(acc[2][1], a2, b1);
      fma2(acc[3][0], a3, b0); fma2(acc[3][1], a3, b1);
    }
    if (ci + 1 < nChunks) {
      int nxt = cur ^ 1;
      As[nxt][lk + 0][lr] = av.x; As[nxt][lk + 1][lr] = av.y;
      As[nxt][lk + 2][lr] = av.z; As[nxt][lk + 3][lr] = av.w;
      Bs[nxt][lk + 0][lr] = bv.x; Bs[nxt][lk + 1][lr] = bv.y;
      Bs[nxt][lk + 2][lr] = bv.z; Bs[nxt][lk + 3][lr] = bv.w;
    }
    __syncthreads();
  }

  const float* __restrict__ bptr = bias + (size_t)t * kH + colBase + tx * 4;
  float4 b4 = *(const float4*)bptr;
#pragma unroll
  for (int m = 0; m < 4; ++m) {
    int row = rowBase + ty * 4 + m;
    float2 lo = unpack2(acc[m][0]);
    float2 hi = unpack2(acc[m][1]);
    float4 o;
    o.x = lo.x + b4.x; o.y = lo.y + b4.y; o.z = hi.x + b4.z; o.w = hi.y + b4.w;
    *(float4*)(g_pre + ((size_t)t * kB + row) * kH + colBase + tx * 4) = o;
  }
}

// ---------------------------------------------------------------------------
// Phase B step t (HMMA tensor path): rows pos < c_t:
//   h_out = tanh(pre[t][pos] + h_in[pos] @ Wh_t^T)  via bf16x3 split mma.sync.
// CTA: 32(pos) x 64(n), 4 warps; warp w -> rows (w&1)*16, cols (w>>1)*32,
// full K=1024 chunked at TK=32 with a double-buffered padded SMEM stage.
__global__ __launch_bounds__(128) void step_kernel(int t) {
  __shared__ __align__(16) __nv_bfloat16 sA[2][2][TM][ASTR];  // [buf][hi/lo]
  __shared__ __align__(16) __nv_bfloat16 sB[2][2][TN][ASTR];

  const int c = g_count[t];
  const int rowBase = blockIdx.x * TM;
  if (rowBase >= c) return;
  const int colBase = blockIdx.y * TN;

  const int pp = t & 1;
  const int tid = threadIdx.x;
  const int w = tid >> 5;
  const int lane = tid & 31;
  const int g = lane >> 2;
  const int tg = lane & 3;
  const int mr = (w & 1) * 16;       // warp row offset in CTA tile
  const int wN = (w >> 1) * 32;      // warp col offset in CTA tile

  const __nv_bfloat16* __restrict__ hh = g_hh[pp];
  const __nv_bfloat16* __restrict__ hl = g_hl[pp];
  const size_t whB = ((size_t)t * kH + colBase) * kH;

  // global loaders: A 128 16B-units (r=tid>>2, u=tid&3); B 256 units (2/thread)
  const int ar = tid >> 2;
  const int au = (tid & 3) * 8;
  const size_t aG = (size_t)(rowBase + ar) * kH + au;
  const int bn0 = tid >> 2, bu0 = (tid & 3) * 8;
  const int bn1 = (tid + 128) >> 2, bu1 = ((tid + 128) & 3) * 8;
  const size_t bG0 = whB + (size_t)bn0 * kH + bu0;
  const size_t bG1 = whB + (size_t)bn1 * kH + bu1;

  // ---- L2 prefetch for step t+1 (deduplicated) ----
  if (t + 1 < kT) {
    if (blockIdx.x == 0) {
      const __nv_bfloat16* f1 = g_whh + whB + (size_t)kH * kH;
      const __nv_bfloat16* f2 = g_whl + whB + (size_t)kH * kH;
      for (int i = tid; i < 1024; i += 128) {
        int n = i >> 4, o = (i & 15) * 64;
        pf_l2(f1 + (size_t)n * kH + o);
        pf_l2(f2 + (size_t)n * kH + o);
      }
    }
    if (blockIdx.y == 0) {
      const float* pp2 = g_pre + ((size_t)(t + 1) * kB + rowBase) * kH;
      for (int i = tid; i < 1024; i += 128) {
        int r = i >> 5, o = (i & 31) * 32;
        pf_l2(pp2 + (size_t)r * kH + o);
      }
    }
  }

  float d[4][4];
#pragma unroll
  for (int nt = 0; nt < 4; ++nt)
#pragma unroll
    for (int j = 0; j < 4; ++j) d[nt][j] = 0.0f;

  // preload chunk 0
  *(uint4*)&sA[0][0][ar][au] = *(const uint4*)(hh + aG);
  *(uint4*)&sA[0][1][ar][au] = *(const uint4*)(hl + aG);
  *(uint4*)&sB[0][0][bn0][bu0] = *(const uint4*)(g_whh + bG0);
  *(uint4*)&sB[0][0][bn1][bu1] = *(const uint4*)(g_whh + bG1);
  *(uint4*)&sB[0][1][bn0][bu0] = *(const uint4*)(g_whl + bG0);
  *(uint4*)&sB[0][1][bn1][bu1] = *(const uint4*)(g_whl + bG1);
  __syncthreads();

  uint4 ra, rl, rb0, rb1, rc0, rc1;
  for (int ch = 0; ch < NCH; ++ch) {
    const int buf = ch & 1;
    if (ch + 1 < NCH) {
      const int k0 = (ch + 1) * TK;
      ra = *(const uint4*)(hh + aG + k0);
      rl = *(const uint4*)(hl + aG + k0);
      rb0 = *(const uint4*)(g_whh + bG0 + k0);
      rb1 = *(const uint4*)(g_whh + bG1 + k0);
      rc0 = *(const uint4*)(g_whl + bG0 + k0);
      rc1 = *(const uint4*)(g_whl + bG1 + k0);
    }
#pragma unroll
    for (int ks = 0; ks < 2; ++ks) {
      const int kc = ks * 16 + tg * 2;
      uint32_t ah0 = *(const uint32_t*)&sA[buf][0][mr + g][kc];
      uint32_t ah1 = *(const uint32_t*)&sA[buf][0][mr + g + 8][kc];
      uint32_t ah2 = *(const uint32_t*)&sA[buf][0][mr + g][kc + 8];
      uint32_t ah3 = *(const uint32_t*)&sA[buf][0][mr + g + 8][kc + 8];
      uint32_t al0 = *(const uint32_t*)&sA[buf][1][mr + g][kc];
      uint32_t al1 = *(const uint32_t*)&sA[buf][1][mr + g + 8][kc];
      uint32_t al2 = *(const uint32_t*)&sA[buf][1][mr + g][kc + 8];
      uint32_t al3 = *(const uint32_t*)&sA[buf][1][mr + g + 8][kc + 8];
#pragma unroll
      for (int nt = 0; nt < 4; ++nt) {
        const int nr = wN + nt * 8 + g;
        uint32_t bh0 = *(const uint32_t*)&sB[buf][0][nr][kc];
        uint32_t bh1 = *(const uint32_t*)&sB[buf][0][nr][kc + 8];
        uint32_t bl0 = *(const uint32_t*)&sB[buf][1][nr][kc];
        uint32_t bl1 = *(const uint32_t*)&sB[buf][1][nr][kc + 8];
        mma_bf16(d[nt], ah0, ah1, ah2, ah3, bh0, bh1);
        mma_bf16(d[nt], ah0, ah1, ah2, ah3, bl0, bl1);
        mma_bf16(d[nt], al0, al1, al2, al3, bh0, bh1);
      }
    }
    if (ch + 1 < NCH) {
      const int nb = (ch + 1) & 1;
      *(uint4*)&sA[nb][0][ar][au] = ra;
      *(uint4*)&sA[nb][1][ar][au] = rl;
      *(uint4*)&sB[nb][0][bn0][bu0] = rb0;
      *(uint4*)&sB[nb][0][bn1][bu1] = rb1;
      *(uint4*)&sB[nb][1][bn0][bu0] = rc0;
      *(uint4*)&sB[nb][1][bn1][bu1] = rc1;
    }
    __syncthreads();
  }

  // ---- epilogue: pre + tanh, write fp32 + bf16 hi/lo h ----
  float* __restrict__ hfO = g_hf[pp ^ 1];
  __nv_bfloat16* __restrict__ hhO = g_hh[pp ^ 1];
  __nv_bfloat16* __restrict__ hlO = g_hl[pp ^ 1];
#pragma unroll
  for (int half = 0; half < 2; ++half) {
    const int row = mr + g + half * 8;
    const int pos = rowBase + row;
    if (pos < c) {
      const size_t base = (size_t)pos * kH + colBase;
      const size_t preB = ((size_t)t * kB + pos) * kH + colBase;
#pragma unroll
      for (int nt = 0; nt < 4; ++nt) {
        const int col = wN + nt * 8 + tg * 2;
        float2 p2 = *(const float2*)(g_pre + preB + col);
        float ox = tanhf(d[nt][half * 2 + 0] + p2.x);
        float oy = tanhf(d[nt][half * 2 + 1] + p2.y);
        float2 o2; o2.x = ox; o2.y = oy;
        *(float2*)(hfO + base + col) = o2;
        __nv_bfloat16 bx = __float2bfloat16(ox);
        __nv_bfloat16 by = __float2bfloat16(oy);
        __nv_bfloat162 hp; hp.x = bx; hp.y = by;
        *(__nv_bfloat162*)(hhO + base + col) = hp;
        __nv_bfloat162 lp;
        lp.x = __float2bfloat16(ox - __bfloat162float(bx));
        lp.y = __float2bfloat16(oy - __bfloat162float(by));
        *(__nv_bfloat162*)(hlO + base + col) = lp;
      }
    }
  }
}

// ---------------------------------------------------------------------------
// out[order[pos]] = h_final[pos] . W_out + b_out (final h in fp32 buffer L&1)
__global__ void out_kernel(const float* __restrict__ Wout,
                           const float* __restrict__ bout,
                           float* __restrict__ out) {
  int pos = blockIdx.x;
  int L = g_lens[pos];
  const float* h = g_hf[L & 1] + (size_t)pos * kH;
  float s = 0.0f;
  for (int i = threadIdx.x; i < kH; i += blockDim.x) s += h[i] * Wout[i];
#pragma unroll
  for (int o = 16; o > 0; o >>= 1) s += __shfl_down_sync(0xffffffffu, s, o);
  __shared__ float red[4];
  if ((threadIdx.x & 31) == 0) red[threadIdx.x >> 5] = s;
  __syncthreads();
  if (threadIdx.x == 0) {
    float tot = red[0] + red[1] + red[2] + red[3];
    out[g_order[pos]] = tot + bout[0];
  }
}

// ---------------------------------------------------------------------------
extern "C" void kernel_launch(void* const* d_in, const int* in_sizes, int n_in,
                              void* d_out, int out_size) {
  const float* x = (const float*)d_in[0];
  const void* seq = d_in[1];
  const float* Wx = (const float*)d_in[2];
  const float* Wh = (const float*)d_in[3];
  const float* bias = (const float*)d_in[4];
  const float* Wout = (const float*)d_in[5];
  const float* bout = (const float*)d_in[6];
  float* out = (float*)d_out;

  init_kernel<<<(kB * kH + 255) / 256, 256>>>();
  sort_kernel<<<1, kB>>>(seq);

  // One-time: bf16 hi/lo split of Wh
  {
    size_t n4 = (size_t)kT * kH * kH / 4;
    split_wh<<<(unsigned)((n4 + 255) / 256), 256>>>(Wh);
  }

  // Phase A: all (t, row-tile, col-tile) GEMMs in one launch
  preA_kernel<<<dim3(kB / 64, kH / 64, kT), 256>>>(x, Wx, bias);

  // Phase B: sequential recurrence on the HMMA tensor path
  for (int t = 0; t < kT; ++t) {
    step_kernel<<<dim3(kB / TM, kH / TN), 128>>>(t);
  }
  out_kernel<<<kB, 128>>>(Wout, bout, out);
}